// round 6
// baseline (speedup 1.0000x reference)
#include <cuda_runtime.h>
#include <cuda_bf16.h>
#include <math.h>
#include <stdint.h>

#define N_SEQ 512
#define LEN   128
#define LL2   256
#define DM    256
#define DT    32
#define DIN   288
#define KP    288
#define KE    384
#define ROWS  (N_SEQ*LEN)   // 65536
#define ROWS2 (N_SEQ*LL2)   // 131072

// ---------------- scratch ----------------------------------------------------
__device__ float g_emb[ROWS*KE];
__device__ float g_x[ROWS*DM];
__device__ float g_tem[ROWS*DT];
__device__ float g_cur[2][ROWS*DM];
__device__ __nv_bfloat16 g_cih[(size_t)ROWS2*KP];
__device__ __nv_bfloat16 g_cil[(size_t)ROWS2*KP];
__device__ __nv_bfloat16 g_wTh[3*4*256*KP];
__device__ __nv_bfloat16 g_wTl[3*4*256*KP];
__device__ __nv_bfloat16 g_qh[(size_t)ROWS2*DM];
__device__ __nv_bfloat16 g_ql[(size_t)ROWS2*DM];
__device__ __nv_bfloat16 g_kh[(size_t)ROWS2*DM];
__device__ __nv_bfloat16 g_kl[(size_t)ROWS2*DM];
__device__ float g_v[ROWS2*DM];
__device__ __nv_bfloat16 g_vTh[(size_t)N_SEQ*DM*LEN];  // [seq][d][key<128]
__device__ __nv_bfloat16 g_vTl[(size_t)N_SEQ*DM*LEN];
__device__ float g_p[N_SEQ*LL2*LEN];
__device__ __nv_bfloat16 g_ph[(size_t)N_SEQ*LL2*LEN];
__device__ __nv_bfloat16 g_pl[(size_t)N_SEQ*LL2*LEN];
__device__ float g_pd[N_SEQ*LL2];
__device__ float g_sv[N_SEQ*DM];
__device__ float g_o[ROWS2*DM];

// ---------------- helpers -----------------------------------------------------
__device__ __forceinline__ uint32_t smem_u32(const void* p) {
    uint32_t a;
    asm("{ .reg .u64 t; cvta.to.shared.u64 t, %1; cvt.u32.u64 %0, t; }" : "=r"(a) : "l"(p));
    return a;
}
#define LDSM4(r0, r1, r2, r3, addr) \
    asm volatile("ldmatrix.sync.aligned.m8n8.x4.shared.b16 {%0,%1,%2,%3}, [%4];" \
        : "=r"(r0), "=r"(r1), "=r"(r2), "=r"(r3) : "r"(addr))
#define MMA16816(c, a, b0, b1) \
    asm volatile("mma.sync.aligned.m16n8k16.row.col.f32.bf16.bf16.f32 " \
        "{%0,%1,%2,%3},{%4,%5,%6,%7},{%8,%9},{%0,%1,%2,%3};" \
        : "+f"((c)[0]), "+f"((c)[1]), "+f"((c)[2]), "+f"((c)[3]) \
        : "r"((a)[0]), "r"((a)[1]), "r"((a)[2]), "r"((a)[3]), "r"(b0), "r"(b1))

// ---------------- shared mma core: C[128,128] += sum of 3 terms ---------------
// A*, B* pre-offset to (m0, 0) / (n0, 0). ktTerm k-tiles (of 32) per term.
__device__ __forceinline__ void mma_core(
    const __nv_bfloat16* A0, const __nv_bfloat16* A1, const __nv_bfloat16* A2,
    const __nv_bfloat16* B0, const __nv_bfloat16* B1, const __nv_bfloat16* B2,
    int lda, int ldb, int ktTerm,
    __nv_bfloat16 (*sA)[5120], __nv_bfloat16 (*sB)[5120],
    float acc[4][4][4])
{
    int tid = threadIdx.x;
    int w = tid >> 5, lane = tid & 31;
    int wm = (w & 1) << 6;
    int wn = (w >> 1) << 5;
    int lr = tid >> 1;
    int lc = (tid & 1) << 1;
    int nkt = 3 * ktTerm;

    {   // prologue: term 0, kk 0
        const uint4* pa = (const uint4*)(A0 + (size_t)lr * lda);
        const uint4* pb = (const uint4*)(B0 + (size_t)lr * ldb);
        uint4 a0 = pa[lc], a1 = pa[lc + 1];
        uint4 b0 = pb[lc], b1 = pb[lc + 1];
        *(uint4*)&sA[0][lr * 40 + lc * 8]       = a0;
        *(uint4*)&sA[0][lr * 40 + (lc + 1) * 8] = a1;
        *(uint4*)&sB[0][lr * 40 + lc * 8]       = b0;
        *(uint4*)&sB[0][lr * 40 + (lc + 1) * 8] = b1;
    }
    __syncthreads();

    uint32_t sA0 = smem_u32(&sA[0][0]);
    uint32_t sB0 = smem_u32(&sB[0][0]);
    int buf = 0;
    int nph = 0, nkk = 32;
    if (nkk == ktTerm * 32) { nkk = 0; nph = 1; }

    for (int kt = 0; kt < nkt; kt++) {
        uint4 na0, na1, nb0, nb1;
        bool more = (kt < nkt - 1);
        if (more) {
            const __nv_bfloat16* Asrc = (nph == 1) ? A1 : ((nph == 2) ? A2 : A0);
            const __nv_bfloat16* Bsrc = (nph == 1) ? B1 : ((nph == 2) ? B2 : B0);
            const uint4* pa = (const uint4*)(Asrc + (size_t)lr * lda + nkk);
            const uint4* pb = (const uint4*)(Bsrc + (size_t)lr * ldb + nkk);
            na0 = pa[lc]; na1 = pa[lc + 1];
            nb0 = pb[lc]; nb1 = pb[lc + 1];
        }
        uint32_t baseA = sA0 + buf * (5120 * 2);
        uint32_t baseB = sB0 + buf * (5120 * 2);
#pragma unroll
        for (int ks = 0; ks < 2; ks++) {
            uint32_t a[4][4];
#pragma unroll
            for (int mf = 0; mf < 4; mf++) {
                uint32_t addr = baseA + ((wm + mf * 16 + (lane & 15)) * 40
                              + (ks * 2 + ((lane >> 4) & 1)) * 8) * 2;
                LDSM4(a[mf][0], a[mf][1], a[mf][2], a[mf][3], addr);
            }
            uint32_t b[2][4];
#pragma unroll
            for (int p = 0; p < 2; p++) {
                uint32_t addr = baseB + ((wn + p * 16 + (lane & 7) + ((lane >> 4) & 1) * 8) * 40
                              + (ks * 2 + ((lane >> 3) & 1)) * 8) * 2;
                LDSM4(b[p][0], b[p][1], b[p][2], b[p][3], addr);
            }
#pragma unroll
            for (int mf = 0; mf < 4; mf++)
#pragma unroll
                for (int nf = 0; nf < 4; nf++)
                    MMA16816(acc[mf][nf], a[mf], b[nf >> 1][(nf & 1) * 2], b[nf >> 1][(nf & 1) * 2 + 1]);
        }
        if (more) {
            int nb = buf ^ 1;
            *(uint4*)&sA[nb][lr * 40 + lc * 8]       = na0;
            *(uint4*)&sA[nb][lr * 40 + (lc + 1) * 8] = na1;
            *(uint4*)&sB[nb][lr * 40 + lc * 8]       = nb0;
            *(uint4*)&sB[nb][lr * 40 + (lc + 1) * 8] = nb1;
            __syncthreads();
            buf = nb;
            nkk += 32;
            if (nkk == ktTerm * 32) { nkk = 0; nph++; }
        }
    }
}

// ---------------- fused prep: gather + tem + zero_cur + wconv ----------------
#define PR0 ((size_t)ROWS*KE)
#define PR1 (PR0 + (size_t)ROWS*16)
#define PR2 (PR1 + (size_t)2*ROWS*DM)
#define PR3 (PR2 + (size_t)3*4*256*KP)
__global__ void k_prep(const int* __restrict__ subj, const int* __restrict__ obj,
                       const int* __restrict__ rel, const float* __restrict__ ent,
                       const float* __restrict__ relw, const float* __restrict__ time,
                       const float* __restrict__ qw, const float* __restrict__ kw,
                       const float* __restrict__ vw) {
    size_t i = (size_t)blockIdx.x * 256 + threadIdx.x;
    if (i < PR0) {
        int row = (int)(i / KE);
        int c   = (int)(i - (size_t)row * KE);
        float v;
        if (c < 128)      v = ent[subj[row] * 128 + c];
        else if (c < 256) v = ent[obj[row] * 128 + (c - 128)];
        else              v = relw[rel[row] * 128 + (c - 256)];
        g_emb[i] = v;
    } else if (i < PR1) {
        size_t j = i - PR0;
        int row = (int)(j >> 4);
        int f   = (int)(j & 15);
        float t = time[row];
        float div = expf((float)(2 * f) * -0.28782313662425576f);
        float arg = t * div;
        float np  = (t > 0.f) ? 1.f : 0.f;
        g_tem[row * DT + 2 * f]     = sinf(arg) * np;
        g_tem[row * DT + 2 * f + 1] = cosf(arg) * np;
    } else if (i < PR2) {
        ((float*)g_cur)[i - PR1] = 0.f;
    } else if (i < PR3) {
        size_t j = i - PR2;
        int k  = (int)(j % KP);
        int n  = (int)((j / KP) & 255);
        int hl = (int)((j / (KP * 256)) & 3);
        int z  = (int)(j / ((size_t)KP * 256 * 4));
        const float* W = (z == 0) ? qw : (z == 1) ? kw : vw;
        float v = W[(hl * DIN + k) * 256 + n];
        __nv_bfloat16 hi = __float2bfloat16(v);
        g_wTh[j] = hi;
        g_wTl[j] = __float2bfloat16(v - __bfloat162float(hi));
    }
}

// ---------------- build ci split-bf16 ----------------------------------------
__global__ void k_build_ci(int h) {
    size_t i = (size_t)blockIdx.x * 256 + threadIdx.x;
    if (i >= (size_t)ROWS2 * KP) return;
    int k   = (int)(i % KP);
    int row = (int)(i / KP);
    int n   = row >> 8;
    int j   = row & 255;
    int jj  = j & 127;
    float v;
    if (k < DM) v = (j < LEN) ? g_x[(n * LEN + j) * DM + k]
                              : g_cur[h][(n * LEN + jj) * DM + k];
    else        v = g_tem[(n * LEN + jj) * DT + (k - DM)];
    __nv_bfloat16 hi = __float2bfloat16(v);
    g_cih[i] = hi;
    g_cil[i] = __float2bfloat16(v - __bfloat162float(hi));
}

// ---------------- QKV mma ------------------------------------------------------
__global__ __launch_bounds__(256) void k_qkv_mma(const float* __restrict__ qb,
                                                 const float* __restrict__ kb,
                                                 const float* __restrict__ vb, int hl) {
    __shared__ __nv_bfloat16 sA[2][5120], sB[2][5120];
    int z  = blockIdx.x >> 1;
    int n0 = (blockIdx.x & 1) << 7;
    int m0 = blockIdx.y << 7;
    const __nv_bfloat16* Ah = g_cih + (size_t)m0 * KP;
    const __nv_bfloat16* Al = g_cil + (size_t)m0 * KP;
    const __nv_bfloat16* Bh = g_wTh + ((size_t)(z * 4 + hl) * 256 + n0) * KP;
    const __nv_bfloat16* Bl = g_wTl + ((size_t)(z * 4 + hl) * 256 + n0) * KP;

    float acc[4][4][4] = {};
    mma_core(Ah, Al, Ah, Bh, Bh, Bl, KP, KP, 9, sA, sB, acc);

    int w = threadIdx.x >> 5, lane = threadIdx.x & 31;
    int wm = (w & 1) << 6, wn = (w >> 1) << 5;
    const float* bias = ((z == 0) ? qb : (z == 1) ? kb : vb) + hl * 256;
    int r0 = lane >> 2, c0 = (lane & 3) << 1;
#pragma unroll
    for (int mf = 0; mf < 4; mf++)
#pragma unroll
        for (int nf = 0; nf < 4; nf++) {
            int row = m0 + wm + mf * 16 + r0;
            int col = n0 + wn + nf * 8 + c0;
#pragma unroll
            for (int q = 0; q < 4; q++) {
                size_t idx = (size_t)(row + (q >> 1) * 8) * DM + col + (q & 1);
                float val = acc[mf][nf][q] + bias[col + (q & 1)];
                if (z == 2) {
                    g_v[idx] = val;
                } else {
                    __nv_bfloat16 hi = __float2bfloat16(val);
                    __nv_bfloat16 lo = __float2bfloat16(val - __bfloat162float(hi));
                    if (z == 0) { g_qh[idx] = hi; g_ql[idx] = lo; }
                    else        { g_kh[idx] = hi; g_kl[idx] = lo; }
                }
            }
        }
}

// ---------------- V transpose (keys 0..127) to bf16 hi/lo ---------------------
__global__ __launch_bounds__(256) void k_vt() {
    __shared__ float tile[128][33];
    int n = blockIdx.y, d0 = blockIdx.x << 5;
    for (int el = threadIdx.x; el < 4096; el += 256) {
        int key = el >> 5, d = el & 31;
        tile[key][d] = g_v[((size_t)n * LL2 + key) * DM + d0 + d];
    }
    __syncthreads();
    for (int el = threadIdx.x; el < 4096; el += 256) {
        int d = el >> 7, key = el & 127;
        float v = tile[key][d];
        __nv_bfloat16 hi = __float2bfloat16(v);
        size_t o = (size_t)n * DM * LEN + (size_t)(d0 + d) * LEN + key;
        g_vTh[o] = hi;
        g_vTl[o] = __float2bfloat16(v - __bfloat162float(hi));
    }
}

__global__ void k_sv() {
    int n = blockIdx.x;
    int d = threadIdx.x;
    const float* vp = g_v + (n * LL2 + LEN) * DM + d;
    float s = 0.f;
#pragma unroll 8
    for (int j = 0; j < LEN; j++) s += vp[j * DM];
    g_sv[n * DM + d] = s;
}

// ---------------- scores mma: P[256,128] = Q @ K^T / 16 -----------------------
__global__ __launch_bounds__(256) void k_scores_mma() {
    __shared__ __nv_bfloat16 sA[2][5120], sB[2][5120];
    int n = blockIdx.y;
    int m0 = blockIdx.x << 7;
    const __nv_bfloat16* Ah = g_qh + ((size_t)n * LL2 + m0) * DM;
    const __nv_bfloat16* Al = g_ql + ((size_t)n * LL2 + m0) * DM;
    const __nv_bfloat16* Bh = g_kh + (size_t)n * LL2 * DM;
    const __nv_bfloat16* Bl = g_kl + (size_t)n * LL2 * DM;

    float acc[4][4][4] = {};
    mma_core(Ah, Al, Ah, Bh, Bh, Bl, DM, DM, 8, sA, sB, acc);

    int w = threadIdx.x >> 5, lane = threadIdx.x & 31;
    int wm = (w & 1) << 6, wn = (w >> 1) << 5;
    int r0 = lane >> 2, c0 = (lane & 3) << 1;
    float* P = g_p + ((size_t)n * LL2 + m0) * LEN;
#pragma unroll
    for (int mf = 0; mf < 4; mf++)
#pragma unroll
        for (int nf = 0; nf < 4; nf++) {
            int row = wm + mf * 16 + r0;
            int col = wn + nf * 8 + c0;
            P[(size_t)row * LEN + col]           = acc[mf][nf][0] * 0.0625f;
            P[(size_t)row * LEN + col + 1]       = acc[mf][nf][1] * 0.0625f;
            P[(size_t)(row + 8) * LEN + col]     = acc[mf][nf][2] * 0.0625f;
            P[(size_t)(row + 8) * LEN + col + 1] = acc[mf][nf][3] * 0.0625f;
        }
}

// ---------------- masked softmax -> bf16 hi/lo probs --------------------------
__global__ __launch_bounds__(256) void k_softmax(const float* __restrict__ time) {
    int warp = threadIdx.x >> 5, lane = threadIdx.x & 31;
    int rowId = blockIdx.x * 8 + warp;
    int n = rowId >> 8;
    int i = rowId & 255;
    const float* row = g_p + (size_t)rowId * LEN;
    __nv_bfloat16* oh = g_ph + (size_t)rowId * LEN;
    __nv_bfloat16* ol = g_pl + (size_t)rowId * LEN;
    const float* tt = time + n * LEN;
    bool bottom = (i >= LEN);
    int iq = bottom ? i - LEN : i;

    float vals[4];
    float mx = -1e30f;
#pragma unroll
    for (int c = 0; c < 4; c++) {
        int j = lane + c * 32;
        float s = row[j];
        bool masked = (j >= iq) || (tt[j] == 0.f);
        s = masked ? -1e9f : s;
        vals[c] = s;
        mx = fmaxf(mx, s);
    }
    float d = 0.f;
    if (bottom) {
        size_t base = (size_t)(n * LL2 + i) * DM / 2;
        const __nv_bfloat162* qh2 = (const __nv_bfloat162*)g_qh + base;
        const __nv_bfloat162* ql2 = (const __nv_bfloat162*)g_ql + base;
        const __nv_bfloat162* kh2 = (const __nv_bfloat162*)g_kh + base;
        const __nv_bfloat162* kl2 = (const __nv_bfloat162*)g_kl + base;
#pragma unroll
        for (int c = 0; c < 4; c++) {
            int idx = lane * 4 + c;
            __nv_bfloat162 a = qh2[idx], b = ql2[idx], e = kh2[idx], f = kl2[idx];
            float qx = __bfloat162float(a.x) + __bfloat162float(b.x);
            float qy = __bfloat162float(a.y) + __bfloat162float(b.y);
            float kx = __bfloat162float(e.x) + __bfloat162float(f.x);
            float ky = __bfloat162float(e.y) + __bfloat162float(f.y);
            d += qx * kx + qy * ky;
        }
#pragma unroll
        for (int off = 16; off; off >>= 1) d += __shfl_xor_sync(0xffffffffu, d, off);
        d *= 0.0625f;
    }
#pragma unroll
    for (int off = 16; off; off >>= 1) mx = fmaxf(mx, __shfl_xor_sync(0xffffffffu, mx, off));

    if (!bottom && mx < -5e8f) {
        __nv_bfloat16 u = __float2bfloat16(1.0f / 256.0f);
#pragma unroll
        for (int c = 0; c < 4; c++) { oh[lane + c * 32] = u; ol[lane + c * 32] = __float2bfloat16(0.f); }
        if (lane == 0) g_pd[rowId] = 1.0f / 256.0f;
        return;
    }
    if (bottom) mx = fmaxf(mx, d);
    float sum = 0.f;
#pragma unroll
    for (int c = 0; c < 4; c++) { vals[c] = expf(vals[c] - mx); sum += vals[c]; }
#pragma unroll
    for (int off = 16; off; off >>= 1) sum += __shfl_xor_sync(0xffffffffu, sum, off);
    float ed = bottom ? expf(d - mx) : 0.f;
    float inv = 1.f / (sum + ed);
#pragma unroll
    for (int c = 0; c < 4; c++) {
        float p = vals[c] * inv;
        __nv_bfloat16 hi = __float2bfloat16(p);
        oh[lane + c * 32] = hi;
        ol[lane + c * 32] = __float2bfloat16(p - __bfloat162float(hi));
    }
    if (lane == 0) g_pd[rowId] = ed * inv;
}

// ---------------- PV mma: O[256,256] = P @ V(:128) + pd*extra -----------------
__global__ __launch_bounds__(256) void k_pv_mma() {
    __shared__ __nv_bfloat16 sA[2][5120], sB[2][5120];
    int n  = blockIdx.z;
    int m0 = blockIdx.y << 7;
    int n0 = blockIdx.x << 7;
    const __nv_bfloat16* Ah = g_ph + ((size_t)n * LL2 + m0) * LEN;
    const __nv_bfloat16* Al = g_pl + ((size_t)n * LL2 + m0) * LEN;
    const __nv_bfloat16* Bh = g_vTh + ((size_t)n * DM + n0) * LEN;
    const __nv_bfloat16* Bl = g_vTl + ((size_t)n * DM + n0) * LEN;

    float acc[4][4][4] = {};
    mma_core(Ah, Al, Ah, Bh, Bh, Bl, LEN, LEN, 4, sA, sB, acc);

    int w = threadIdx.x >> 5, lane = threadIdx.x & 31;
    int wm = (w & 1) << 6, wn = (w >> 1) << 5;
    int r0 = lane >> 2, c0 = (lane & 3) << 1;
    const float* V = g_v + (size_t)n * LL2 * DM;
    float* O = g_o + (size_t)n * LL2 * DM;
#pragma unroll
    for (int mf = 0; mf < 4; mf++)
#pragma unroll
        for (int nf = 0; nf < 4; nf++) {
            int row = m0 + wm + mf * 16 + r0;
            int col = n0 + wn + nf * 8 + c0;
#pragma unroll
            for (int q = 0; q < 4; q++) {
                int r = row + (q >> 1) * 8;
                int c = col + (q & 1);
                float pd = g_pd[n * LL2 + r];
                float extra = (r < LEN) ? g_sv[n * DM + c] : V[(size_t)r * DM + c];
                O[(size_t)r * DM + c] = acc[mf][nf][q] + pd * extra;
            }
        }
}

// ---------------- residual update ---------------------------------------------
__global__ void k_update(const float* __restrict__ time, int h) {
    int i = blockIdx.x * 256 + threadIdx.x;
    if (i >= ROWS * DM) return;
    int row = i >> 8;
    int d   = i & 255;
    int n   = row >> 7;
    int l   = row & 127;
    float top = g_o[(n * LL2 + l) * DM + d];
    float bot = g_o[(n * LL2 + LEN + l) * DM + d];
    float np  = (time[row] > 0.f) ? 1.f : 0.f;
    g_cur[h][i] += tanhf(bot * np);
    g_x[i] = top;
}

// ---------------- FFMA GEMM for the input projection --------------------------
__device__ __forceinline__ void gemm_compute(const float (*As)[140], const float (*Bs)[128],
                                             float acc[8][8], int tx, int ty) {
#pragma unroll
    for (int k = 0; k < 8; k++) {
        float a[8], b[8];
        *(float4*)(a)     = *(const float4*)&As[k][ty * 4];
        *(float4*)(a + 4) = *(const float4*)&As[k][64 + ty * 4];
        *(float4*)(b)     = *(const float4*)&Bs[k][tx * 4];
        *(float4*)(b + 4) = *(const float4*)&Bs[k][64 + tx * 4];
#pragma unroll
        for (int i = 0; i < 8; i++)
#pragma unroll
            for (int j = 0; j < 8; j++)
                acc[i][j] += a[i] * b[j];
    }
}

__global__ __launch_bounds__(256) void k_gemm_x(const float* __restrict__ W,
                                                const float* __restrict__ bias) {
    __shared__ float As[2][8][140];
    __shared__ float Bs[2][8][128];
    float acc[8][8] = {};
    int m0 = blockIdx.y << 7, n0 = blockIdx.x << 7;
    int tid = threadIdx.x;
    int tx = tid & 15, ty = tid >> 4;
    int ar = tid >> 1, kg = (tid & 1) << 2;
    int br = tid >> 5, bc = (tid & 31) << 2;

    float4 a = *(const float4*)(g_emb + (m0 + ar) * KE + kg);
    float4 b = *(const float4*)(W + br * DM + n0 + bc);
    As[0][kg][ar] = a.x; As[0][kg + 1][ar] = a.y; As[0][kg + 2][ar] = a.z; As[0][kg + 3][ar] = a.w;
    *(float4*)&Bs[0][br][bc] = b;
    __syncthreads();

    int buf = 0;
    for (int k0 = 8; k0 < KE; k0 += 8) {
        float4 an = *(const float4*)(g_emb + (m0 + ar) * KE + k0 + kg);
        float4 bn = *(const float4*)(W + (k0 + br) * DM + n0 + bc);
        gemm_compute(As[buf], Bs[buf], acc, tx, ty);
        int nb = buf ^ 1;
        As[nb][kg][ar] = an.x; As[nb][kg + 1][ar] = an.y; As[nb][kg + 2][ar] = an.z; As[nb][kg + 3][ar] = an.w;
        *(float4*)&Bs[nb][br][bc] = bn;
        __syncthreads();
        buf = nb;
    }
    gemm_compute(As[buf], Bs[buf], acc, tx, ty);

#pragma unroll
    for (int i = 0; i < 8; i++) {
        int r = m0 + ((i < 4) ? (ty << 2) + i : 64 + (ty << 2) + i - 4);
#pragma unroll
        for (int j = 0; j < 8; j++) {
            int c = n0 + ((j < 4) ? (tx << 2) + j : 64 + (tx << 2) + j - 4);
            g_x[r * DM + c] = acc[i][j] + bias[c];
        }
    }
}

// ---------------- final MLP head ----------------------------------------------
__global__ __launch_bounds__(256) void k_head(const float* __restrict__ w1,
                                              const float* __restrict__ b1,
                                              const float* __restrict__ w2,
                                              const float* __restrict__ b2,
                                              float* __restrict__ out) {
    int n = blockIdx.x;
    int t = threadIdx.x;
    __shared__ float sl[512];
    __shared__ float sh[256];
    sl[t]       = g_cur[0][(n * LEN + LEN - 1) * DM + t];
    sl[256 + t] = g_cur[1][(n * LEN + LEN - 1) * DM + t];
    __syncthreads();
    float acc = b1[t];
    for (int k = 0; k < 512; k++) acc += sl[k] * w1[k * DM + t];
    float x = acc;
    float g = 0.5f * x * (1.f + erff(x * 0.7071067811865476f));
    sh[t] = g * w2[t];
    __syncthreads();
    for (int s = 128; s > 0; s >>= 1) {
        if (t < s) sh[t] += sh[t + s];
        __syncthreads();
    }
    if (t == 0) out[n] = sh[0] + b2[0];
}

// ---------------- launch ------------------------------------------------------
extern "C" void kernel_launch(void* const* d_in, const int* in_sizes, int n_in,
                              void* d_out, int out_size) {
    const int*   subj = (const int*)d_in[0];
    const int*   obj  = (const int*)d_in[1];
    const int*   rel  = (const int*)d_in[2];
    const float* time = (const float*)d_in[3];
    const float* ent  = (const float*)d_in[4];
    const float* relw = (const float*)d_in[5];
    const float* in_w = (const float*)d_in[6];
    const float* in_b = (const float*)d_in[7];
    const float* q_w  = (const float*)d_in[8];
    const float* q_b  = (const float*)d_in[9];
    const float* k_w  = (const float*)d_in[10];
    const float* k_b  = (const float*)d_in[11];
    const float* v_w  = (const float*)d_in[12];
    const float* v_b  = (const float*)d_in[13];
    const float* w1   = (const float*)d_in[14];
    const float* b1   = (const float*)d_in[15];
    const float* w2   = (const float*)d_in[16];
    const float* b2   = (const float*)d_in[17];
    float* out = (float*)d_out;

    k_prep<<<(unsigned)((PR3 + 255) / 256), 256>>>(subj, obj, rel, ent, relw, time, q_w, k_w, v_w);
    k_gemm_x<<<dim3(DM / 128, ROWS / 128), 256>>>(in_w, in_b);

    for (int h = 0; h < 2; h++) {
        for (int l = 0; l < 2; l++) {
            int hl = h * 2 + l;
            k_build_ci<<<(int)(((size_t)ROWS2 * KP + 255) / 256), 256>>>(h);
            k_qkv_mma<<<dim3(6, ROWS2 / 128), 256>>>(q_b, k_b, v_b, hl);
            k_vt<<<dim3(8, N_SEQ), 256>>>();
            k_sv<<<N_SEQ, 256>>>();
            k_scores_mma<<<dim3(2, N_SEQ), 256>>>();
            k_softmax<<<(N_SEQ * LL2) / 8, 256>>>(time);
            k_pv_mma<<<dim3(2, 2, N_SEQ), 256>>>();
            k_update<<<(ROWS * DM + 255) / 256, 256>>>(time, h);
        }
    }
    k_head<<<N_SEQ, 256>>>(w1, b1, w2, b2, out);
}

// round 8
// speedup vs baseline: 1.2690x; 1.2690x over previous
#include <cuda_runtime.h>
#include <cuda_bf16.h>
#include <math.h>
#include <stdint.h>

#define N_SEQ 512
#define LEN   128
#define LL2   256
#define DM    256
#define DT    32
#define DIN   288
#define KP    288
#define KE    384
#define ROWS  (N_SEQ*LEN)   // 65536
#define ROWS2 (N_SEQ*LL2)   // 131072

#define TILE_B   10240               // 128 rows * 80 bytes
#define SMEM_MMA (8 * TILE_B)        // 4 tiles x 2 buffers = 81920

// ---------------- scratch ----------------------------------------------------
__device__ float g_emb[ROWS*KE];
__device__ float g_x[ROWS*DM];
__device__ float g_tem[ROWS*DT];
__device__ float g_cur[2][ROWS*DM];
__device__ __nv_bfloat16 g_cih[(size_t)ROWS2*KP];
__device__ __nv_bfloat16 g_cil[(size_t)ROWS2*KP];
__device__ __nv_bfloat16 g_wTh[3*4*256*KP];
__device__ __nv_bfloat16 g_wTl[3*4*256*KP];
__device__ __nv_bfloat16 g_qh[(size_t)ROWS2*DM];
__device__ __nv_bfloat16 g_ql[(size_t)ROWS2*DM];
__device__ __nv_bfloat16 g_kh[(size_t)ROWS2*DM];
__device__ __nv_bfloat16 g_kl[(size_t)ROWS2*DM];
__device__ float g_v[ROWS2*DM];
__device__ __nv_bfloat16 g_vTh[(size_t)N_SEQ*DM*LEN];
__device__ __nv_bfloat16 g_vTl[(size_t)N_SEQ*DM*LEN];
__device__ float g_p[N_SEQ*LL2*LEN];
__device__ __nv_bfloat16 g_ph[(size_t)N_SEQ*LL2*LEN];
__device__ __nv_bfloat16 g_pl[(size_t)N_SEQ*LL2*LEN];
__device__ float g_pd[N_SEQ*LL2];
__device__ float g_sv[N_SEQ*DM];
__device__ float g_o[ROWS2*DM];

// ---------------- helpers -----------------------------------------------------
__device__ __forceinline__ uint32_t smem_u32(const void* p) {
    uint32_t a;
    asm("{ .reg .u64 t; cvta.to.shared.u64 t, %1; cvt.u32.u64 %0, t; }" : "=r"(a) : "l"(p));
    return a;
}
#define LDSM4(r0, r1, r2, r3, addr) \
    asm volatile("ldmatrix.sync.aligned.m8n8.x4.shared.b16 {%0,%1,%2,%3}, [%4];" \
        : "=r"(r0), "=r"(r1), "=r"(r2), "=r"(r3) : "r"(addr))
#define MMA16816(c, a, b0, b1) \
    asm volatile("mma.sync.aligned.m16n8k16.row.col.f32.bf16.bf16.f32 " \
        "{%0,%1,%2,%3},{%4,%5,%6,%7},{%8,%9},{%0,%1,%2,%3};" \
        : "+f"((c)[0]), "+f"((c)[1]), "+f"((c)[2]), "+f"((c)[3]) \
        : "r"((a)[0]), "r"((a)[1]), "r"((a)[2]), "r"((a)[3]), "r"(b0), "r"(b1))
#define CPASYNC16(dst, src) \
    asm volatile("cp.async.ca.shared.global [%0], [%1], 16;" :: "r"(dst), "l"(src))
#define CPCOMMIT() asm volatile("cp.async.commit_group;" ::: "memory")
#define CPWAIT0()  asm volatile("cp.async.wait_group 0;" ::: "memory")
#define CPWAIT1()  asm volatile("cp.async.wait_group 1;" ::: "memory")

// ---------------- fused 3-term mma core ---------------------------------------
// C[128,128] = Ah@Bh^T + Al@Bh^T + Ah@Bl^T over K = nkt*32. A,B pre-offset.
__device__ __forceinline__ void mma_core3(
    const __nv_bfloat16* Ah, const __nv_bfloat16* Al,
    const __nv_bfloat16* Bh, const __nv_bfloat16* Bl,
    int lda, int ldb, int nkt, uint32_t sbase, float acc[4][4][4])
{
    int tid = threadIdx.x;
    int w = tid >> 5, lane = tid & 31;
    int wm = (w & 1) << 6;
    int wn = (w >> 1) << 5;
    int lr = tid >> 1;
    int c2 = (tid & 1) << 1;          // chunk pair 0 / 2

    const char* pAh = (const char*)(Ah + (size_t)lr * lda) + c2 * 16;
    const char* pAl = (const char*)(Al + (size_t)lr * lda) + c2 * 16;
    const char* pBh = (const char*)(Bh + (size_t)lr * ldb) + c2 * 16;
    const char* pBl = (const char*)(Bl + (size_t)lr * ldb) + c2 * 16;
    uint32_t sdst = sbase + lr * 80 + c2 * 16;

    // prologue: ktile 0 -> buffer 0
    {
        CPASYNC16(sdst,              pAh);       CPASYNC16(sdst + 16,              pAh + 16);
        CPASYNC16(sdst + TILE_B,     pAl);       CPASYNC16(sdst + TILE_B + 16,     pAl + 16);
        CPASYNC16(sdst + 2*TILE_B,   pBh);       CPASYNC16(sdst + 2*TILE_B + 16,   pBh + 16);
        CPASYNC16(sdst + 3*TILE_B,   pBl);       CPASYNC16(sdst + 3*TILE_B + 16,   pBl + 16);
        CPCOMMIT();
    }

    int buf = 0;
    for (int kt = 0; kt < nkt; kt++) {
        bool more = (kt + 1 < nkt);
        if (more) {
            int off = (kt + 1) * 64;             // 32 bf16 = 64 bytes
            uint32_t d = sdst + (buf ^ 1) * (4 * TILE_B);
            CPASYNC16(d,              pAh + off);       CPASYNC16(d + 16,              pAh + off + 16);
            CPASYNC16(d + TILE_B,     pAl + off);       CPASYNC16(d + TILE_B + 16,     pAl + off + 16);
            CPASYNC16(d + 2*TILE_B,   pBh + off);       CPASYNC16(d + 2*TILE_B + 16,   pBh + off + 16);
            CPASYNC16(d + 3*TILE_B,   pBl + off);       CPASYNC16(d + 3*TILE_B + 16,   pBl + off + 16);
            CPCOMMIT();
            CPWAIT1();
        } else {
            CPWAIT0();
        }
        __syncthreads();

        uint32_t bAh = sbase + buf * (4 * TILE_B);
        uint32_t bAl = bAh + TILE_B;
        uint32_t bBh = bAh + 2 * TILE_B;
        uint32_t bBl = bAh + 3 * TILE_B;
#pragma unroll
        for (int ks = 0; ks < 2; ks++) {
            uint32_t arow = (uint32_t)((lane & 15)) * 80 + (uint32_t)(ks * 2 + ((lane >> 4) & 1)) * 16;
            uint32_t brow = (uint32_t)((lane & 7) + ((lane >> 4) & 1) * 8) * 80
                          + (uint32_t)(ks * 2 + ((lane >> 3) & 1)) * 16;
            uint32_t bh[2][4], bl[2][4];
#pragma unroll
            for (int p = 0; p < 2; p++) {
                uint32_t ad = (uint32_t)(wn + p * 16) * 80 + brow;
                LDSM4(bh[p][0], bh[p][1], bh[p][2], bh[p][3], bBh + ad);
                LDSM4(bl[p][0], bl[p][1], bl[p][2], bl[p][3], bBl + ad);
            }
            uint32_t a[4][4];
#pragma unroll
            for (int mf = 0; mf < 4; mf++) {
                uint32_t ad = (uint32_t)(wm + mf * 16) * 80 + arow;
                LDSM4(a[mf][0], a[mf][1], a[mf][2], a[mf][3], bAh + ad);
            }
#pragma unroll
            for (int mf = 0; mf < 4; mf++)
#pragma unroll
                for (int nf = 0; nf < 4; nf++) {
                    MMA16816(acc[mf][nf], a[mf], bh[nf >> 1][(nf & 1) * 2], bh[nf >> 1][(nf & 1) * 2 + 1]);
                    MMA16816(acc[mf][nf], a[mf], bl[nf >> 1][(nf & 1) * 2], bl[nf >> 1][(nf & 1) * 2 + 1]);
                }
#pragma unroll
            for (int mf = 0; mf < 4; mf++) {
                uint32_t ad = (uint32_t)(wm + mf * 16) * 80 + arow;
                LDSM4(a[mf][0], a[mf][1], a[mf][2], a[mf][3], bAl + ad);
            }
#pragma unroll
            for (int mf = 0; mf < 4; mf++)
#pragma unroll
                for (int nf = 0; nf < 4; nf++)
                    MMA16816(acc[mf][nf], a[mf], bh[nf >> 1][(nf & 1) * 2], bh[nf >> 1][(nf & 1) * 2 + 1]);
        }
        __syncthreads();
        buf ^= 1;
    }
}

// ---------------- fused prep ---------------------------------------------------
#define PR0 ((size_t)ROWS*KE)
#define PR1 (PR0 + (size_t)ROWS*16)
#define PR2 (PR1 + (size_t)2*ROWS*DM)
#define PR3 (PR2 + (size_t)3*4*256*KP)
__global__ void k_prep(const int* __restrict__ subj, const int* __restrict__ obj,
                       const int* __restrict__ rel, const float* __restrict__ ent,
                       const float* __restrict__ relw, const float* __restrict__ time,
                       const float* __restrict__ qw, const float* __restrict__ kw,
                       const float* __restrict__ vw) {
    size_t i = (size_t)blockIdx.x * 256 + threadIdx.x;
    if (i < PR0) {
        int row = (int)(i / KE);
        int c   = (int)(i - (size_t)row * KE);
        float v;
        if (c < 128)      v = ent[subj[row] * 128 + c];
        else if (c < 256) v = ent[obj[row] * 128 + (c - 128)];
        else              v = relw[rel[row] * 128 + (c - 256)];
        g_emb[i] = v;
    } else if (i < PR1) {
        size_t j = i - PR0;
        int row = (int)(j >> 4);
        int f   = (int)(j & 15);
        float t = time[row];
        float div = expf((float)(2 * f) * -0.28782313662425576f);
        float arg = t * div;
        float np  = (t > 0.f) ? 1.f : 0.f;
        g_tem[row * DT + 2 * f]     = sinf(arg) * np;
        g_tem[row * DT + 2 * f + 1] = cosf(arg) * np;
    } else if (i < PR2) {
        ((float*)g_cur)[i - PR1] = 0.f;
    } else if (i < PR3) {
        size_t j = i - PR2;
        int k  = (int)(j % KP);
        int n  = (int)((j / KP) & 255);
        int hl = (int)((j / (KP * 256)) & 3);
        int z  = (int)(j / ((size_t)KP * 256 * 4));
        const float* W = (z == 0) ? qw : (z == 1) ? kw : vw;
        float v = W[(hl * DIN + k) * 256 + n];
        __nv_bfloat16 hi = __float2bfloat16(v);
        g_wTh[j] = hi;
        g_wTl[j] = __float2bfloat16(v - __bfloat162float(hi));
    }
}

__global__ void k_build_ci(int h) {
    size_t i = (size_t)blockIdx.x * 256 + threadIdx.x;
    if (i >= (size_t)ROWS2 * KP) return;
    int k   = (int)(i % KP);
    int row = (int)(i / KP);
    int n   = row >> 8;
    int j   = row & 255;
    int jj  = j & 127;
    float v;
    if (k < DM) v = (j < LEN) ? g_x[(n * LEN + j) * DM + k]
                              : g_cur[h][(n * LEN + jj) * DM + k];
    else        v = g_tem[(n * LEN + jj) * DT + (k - DM)];
    __nv_bfloat16 hi = __float2bfloat16(v);
    g_cih[i] = hi;
    g_cil[i] = __float2bfloat16(v - __bfloat162float(hi));
}

// ---------------- QKV mma ------------------------------------------------------
__global__ __launch_bounds__(256, 2) void k_qkv_mma(const float* __restrict__ qb,
                                                    const float* __restrict__ kb,
                                                    const float* __restrict__ vb, int hl) {
    extern __shared__ __nv_bfloat16 smem_dyn[];
    uint32_t sbase = smem_u32(smem_dyn);
    int z  = blockIdx.x >> 1;
    int n0 = (blockIdx.x & 1) << 7;
    int m0 = blockIdx.y << 7;

    float acc[4][4][4] = {};
    mma_core3(g_cih + (size_t)m0 * KP, g_cil + (size_t)m0 * KP,
              g_wTh + ((size_t)(z * 4 + hl) * 256 + n0) * KP,
              g_wTl + ((size_t)(z * 4 + hl) * 256 + n0) * KP,
              KP, KP, 9, sbase, acc);

    int w = threadIdx.x >> 5, lane = threadIdx.x & 31;
    int wm = (w & 1) << 6, wn = (w >> 1) << 5;
    const float* bias = ((z == 0) ? qb : (z == 1) ? kb : vb) + hl * 256;
    int r0 = lane >> 2, c0 = (lane & 3) << 1;
#pragma unroll
    for (int mf = 0; mf < 4; mf++)
#pragma unroll
        for (int nf = 0; nf < 4; nf++) {
            int row = m0 + wm + mf * 16 + r0;
            int col = n0 + wn + nf * 8 + c0;
#pragma unroll
            for (int q = 0; q < 4; q++) {
                size_t idx = (size_t)(row + (q >> 1) * 8) * DM + col + (q & 1);
                float val = acc[mf][nf][q] + bias[col + (q & 1)];
                if (z == 2) {
                    g_v[idx] = val;
                } else {
                    __nv_bfloat16 hi = __float2bfloat16(val);
                    __nv_bfloat16 lo = __float2bfloat16(val - __bfloat162float(hi));
                    if (z == 0) { g_qh[idx] = hi; g_ql[idx] = lo; }
                    else        { g_kh[idx] = hi; g_kl[idx] = lo; }
                }
            }
        }
}

// ---------------- V transpose + sv ---------------------------------------------
__global__ __launch_bounds__(256) void k_vt() {
    __shared__ float tile[128][33];
    int n = blockIdx.y, d0 = blockIdx.x << 5;
    for (int el = threadIdx.x; el < 4096; el += 256) {
        int key = el >> 5, d = el & 31;
        tile[key][d] = g_v[((size_t)n * LL2 + key) * DM + d0 + d];
    }
    __syncthreads();
    for (int el = threadIdx.x; el < 4096; el += 256) {
        int d = el >> 7, key = el & 127;
        float v = tile[key][d];
        __nv_bfloat16 hi = __float2bfloat16(v);
        size_t o = (size_t)n * DM * LEN + (size_t)(d0 + d) * LEN + key;
        g_vTh[o] = hi;
        g_vTl[o] = __float2bfloat16(v - __bfloat162float(hi));
    }
}

__global__ void k_sv() {
    int n = blockIdx.x;
    int d = threadIdx.x;
    const float* vp = g_v + (n * LL2 + LEN) * DM + d;
    float s = 0.f;
#pragma unroll 8
    for (int j = 0; j < LEN; j++) s += vp[j * DM];
    g_sv[n * DM + d] = s;
}

// ---------------- scores mma ---------------------------------------------------
__global__ __launch_bounds__(256, 2) void k_scores_mma() {
    extern __shared__ __nv_bfloat16 smem_dyn[];
    uint32_t sbase = smem_u32(smem_dyn);
    int n = blockIdx.y;
    int m0 = blockIdx.x << 7;

    float acc[4][4][4] = {};
    mma_core3(g_qh + ((size_t)n * LL2 + m0) * DM, g_ql + ((size_t)n * LL2 + m0) * DM,
              g_kh + (size_t)n * LL2 * DM, g_kl + (size_t)n * LL2 * DM,
              DM, DM, 8, sbase, acc);

    int w = threadIdx.x >> 5, lane = threadIdx.x & 31;
    int wm = (w & 1) << 6, wn = (w >> 1) << 5;
    int r0 = lane >> 2, c0 = (lane & 3) << 1;
    float* P = g_p + ((size_t)n * LL2 + m0) * LEN;
#pragma unroll
    for (int mf = 0; mf < 4; mf++)
#pragma unroll
        for (int nf = 0; nf < 4; nf++) {
            int row = wm + mf * 16 + r0;
            int col = wn + nf * 8 + c0;
            P[(size_t)row * LEN + col]           = acc[mf][nf][0] * 0.0625f;
            P[(size_t)row * LEN + col + 1]       = acc[mf][nf][1] * 0.0625f;
            P[(size_t)(row + 8) * LEN + col]     = acc[mf][nf][2] * 0.0625f;
            P[(size_t)(row + 8) * LEN + col + 1] = acc[mf][nf][3] * 0.0625f;
        }
}

// ---------------- masked softmax -> bf16 hi/lo ---------------------------------
__global__ __launch_bounds__(256) void k_softmax(const float* __restrict__ time) {
    int warp = threadIdx.x >> 5, lane = threadIdx.x & 31;
    int rowId = blockIdx.x * 8 + warp;
    int n = rowId >> 8;
    int i = rowId & 255;
    const float* row = g_p + (size_t)rowId * LEN;
    __nv_bfloat16* oh = g_ph + (size_t)rowId * LEN;
    __nv_bfloat16* ol = g_pl + (size_t)rowId * LEN;
    const float* tt = time + n * LEN;
    bool bottom = (i >= LEN);
    int iq = bottom ? i - LEN : i;

    float vals[4];
    float mx = -1e30f;
#pragma unroll
    for (int c = 0; c < 4; c++) {
        int j = lane + c * 32;
        float s = row[j];
        bool masked = (j >= iq) || (tt[j] == 0.f);
        s = masked ? -1e9f : s;
        vals[c] = s;
        mx = fmaxf(mx, s);
    }
    float d = 0.f;
    if (bottom) {
        size_t base = (size_t)(n * LL2 + i) * DM / 2;
        const __nv_bfloat162* qh2 = (const __nv_bfloat162*)g_qh + base;
        const __nv_bfloat162* ql2 = (const __nv_bfloat162*)g_ql + base;
        const __nv_bfloat162* kh2 = (const __nv_bfloat162*)g_kh + base;
        const __nv_bfloat162* kl2 = (const __nv_bfloat162*)g_kl + base;
#pragma unroll
        for (int c = 0; c < 4; c++) {
            int idx = lane * 4 + c;
            __nv_bfloat162 a = qh2[idx], b = ql2[idx], e = kh2[idx], f = kl2[idx];
            float qx = __bfloat162float(a.x) + __bfloat162float(b.x);
            float qy = __bfloat162float(a.y) + __bfloat162float(b.y);
            float kx = __bfloat162float(e.x) + __bfloat162float(f.x);
            float ky = __bfloat162float(e.y) + __bfloat162float(f.y);
            d += qx * kx + qy * ky;
        }
#pragma unroll
        for (int off = 16; off; off >>= 1) d += __shfl_xor_sync(0xffffffffu, d, off);
        d *= 0.0625f;
    }
#pragma unroll
    for (int off = 16; off; off >>= 1) mx = fmaxf(mx, __shfl_xor_sync(0xffffffffu, mx, off));

    if (!bottom && mx < -5e8f) {
        __nv_bfloat16 u = __float2bfloat16(1.0f / 256.0f);
#pragma unroll
        for (int c = 0; c < 4; c++) { oh[lane + c * 32] = u; ol[lane + c * 32] = __float2bfloat16(0.f); }
        if (lane == 0) g_pd[rowId] = 1.0f / 256.0f;
        return;
    }
    if (bottom) mx = fmaxf(mx, d);
    float sum = 0.f;
#pragma unroll
    for (int c = 0; c < 4; c++) { vals[c] = expf(vals[c] - mx); sum += vals[c]; }
#pragma unroll
    for (int off = 16; off; off >>= 1) sum += __shfl_xor_sync(0xffffffffu, sum, off);
    float ed = bottom ? expf(d - mx) : 0.f;
    float inv = 1.f / (sum + ed);
#pragma unroll
    for (int c = 0; c < 4; c++) {
        float p = vals[c] * inv;
        __nv_bfloat16 hi = __float2bfloat16(p);
        oh[lane + c * 32] = hi;
        ol[lane + c * 32] = __float2bfloat16(p - __bfloat162float(hi));
    }
    if (lane == 0) g_pd[rowId] = ed * inv;
}

// ---------------- PV mma -------------------------------------------------------
__global__ __launch_bounds__(256, 2) void k_pv_mma() {
    extern __shared__ __nv_bfloat16 smem_dyn[];
    uint32_t sbase = smem_u32(smem_dyn);
    int n  = blockIdx.z;
    int m0 = blockIdx.y << 7;
    int n0 = blockIdx.x << 7;

    float acc[4][4][4] = {};
    mma_core3(g_ph + ((size_t)n * LL2 + m0) * LEN, g_pl + ((size_t)n * LL2 + m0) * LEN,
              g_vTh + ((size_t)n * DM + n0) * LEN, g_vTl + ((size_t)n * DM + n0) * LEN,
              LEN, LEN, 4, sbase, acc);

    int w = threadIdx.x >> 5, lane = threadIdx.x & 31;
    int wm = (w & 1) << 6, wn = (w >> 1) << 5;
    int r0 = lane >> 2, c0 = (lane & 3) << 1;
    const float* V = g_v + (size_t)n * LL2 * DM;
    float* O = g_o + (size_t)n * LL2 * DM;
#pragma unroll
    for (int mf = 0; mf < 4; mf++)
#pragma unroll
        for (int nf = 0; nf < 4; nf++) {
            int row = m0 + wm + mf * 16 + r0;
            int col = n0 + wn + nf * 8 + c0;
#pragma unroll
            for (int q = 0; q < 4; q++) {
                int r = row + (q >> 1) * 8;
                int c = col + (q & 1);
                float pd = g_pd[n * LL2 + r];
                float extra = (r < LEN) ? g_sv[n * DM + c] : V[(size_t)r * DM + c];
                O[(size_t)r * DM + c] = acc[mf][nf][q] + pd * extra;
            }
        }
}

// ---------------- residual update ----------------------------------------------
__global__ void k_update(const float* __restrict__ time, int h) {
    int i = blockIdx.x * 256 + threadIdx.x;
    if (i >= ROWS * DM) return;
    int row = i >> 8;
    int d   = i & 255;
    int n   = row >> 7;
    int l   = row & 127;
    float top = g_o[(n * LL2 + l) * DM + d];
    float bot = g_o[(n * LL2 + LEN + l) * DM + d];
    float np  = (time[row] > 0.f) ? 1.f : 0.f;
    g_cur[h][i] += tanhf(bot * np);
    g_x[i] = top;
}

// ---------------- FFMA GEMM for input projection -------------------------------
__device__ __forceinline__ void gemm_compute(const float (*As)[140], const float (*Bs)[128],
                                             float acc[8][8], int tx, int ty) {
#pragma unroll
    for (int k = 0; k < 8; k++) {
        float a[8], b[8];
        *(float4*)(a)     = *(const float4*)&As[k][ty * 4];
        *(float4*)(a + 4) = *(const float4*)&As[k][64 + ty * 4];
        *(float4*)(b)     = *(const float4*)&Bs[k][tx * 4];
        *(float4*)(b + 4) = *(const float4*)&Bs[k][64 + tx * 4];
#pragma unroll
        for (int i = 0; i < 8; i++)
#pragma unroll
            for (int j = 0; j < 8; j++)
                acc[i][j] += a[i] * b[j];
    }
}

__global__ __launch_bounds__(256) void k_gemm_x(const float* __restrict__ W,
                                                const float* __restrict__ bias) {
    __shared__ float As[2][8][140];
    __shared__ float Bs[2][8][128];
    float acc[8][8] = {};
    int m0 = blockIdx.y << 7, n0 = blockIdx.x << 7;
    int tid = threadIdx.x;
    int tx = tid & 15, ty = tid >> 4;
    int ar = tid >> 1, kg = (tid & 1) << 2;
    int br = tid >> 5, bc = (tid & 31) << 2;

    float4 a = *(const float4*)(g_emb + (m0 + ar) * KE + kg);
    float4 b = *(const float4*)(W + br * DM + n0 + bc);
    As[0][kg][ar] = a.x; As[0][kg + 1][ar] = a.y; As[0][kg + 2][ar] = a.z; As[0][kg + 3][ar] = a.w;
    *(float4*)&Bs[0][br][bc] = b;
    __syncthreads();

    int buf = 0;
    for (int k0 = 8; k0 < KE; k0 += 8) {
        float4 an = *(const float4*)(g_emb + (m0 + ar) * KE + k0 + kg);
        float4 bn = *(const float4*)(W + (k0 + br) * DM + n0 + bc);
        gemm_compute(As[buf], Bs[buf], acc, tx, ty);
        int nb = buf ^ 1;
        As[nb][kg][ar] = an.x; As[nb][kg + 1][ar] = an.y; As[nb][kg + 2][ar] = an.z; As[nb][kg + 3][ar] = an.w;
        *(float4*)&Bs[nb][br][bc] = bn;
        __syncthreads();
        buf = nb;
    }
    gemm_compute(As[buf], Bs[buf], acc, tx, ty);

#pragma unroll
    for (int i = 0; i < 8; i++) {
        int r = m0 + ((i < 4) ? (ty << 2) + i : 64 + (ty << 2) + i - 4);
#pragma unroll
        for (int j = 0; j < 8; j++) {
            int c = n0 + ((j < 4) ? (tx << 2) + j : 64 + (tx << 2) + j - 4);
            g_x[r * DM + c] = acc[i][j] + bias[c];
        }
    }
}

// ---------------- final MLP head -----------------------------------------------
__global__ __launch_bounds__(256) void k_head(const float* __restrict__ w1,
                                              const float* __restrict__ b1,
                                              const float* __restrict__ w2,
                                              const float* __restrict__ b2,
                                              float* __restrict__ out) {
    int n = blockIdx.x;
    int t = threadIdx.x;
    __shared__ float sl[512];
    __shared__ float sh[256];
    sl[t]       = g_cur[0][(n * LEN + LEN - 1) * DM + t];
    sl[256 + t] = g_cur[1][(n * LEN + LEN - 1) * DM + t];
    __syncthreads();
    float acc = b1[t];
    for (int k = 0; k < 512; k++) acc += sl[k] * w1[k * DM + t];
    float x = acc;
    float g = 0.5f * x * (1.f + erff(x * 0.7071067811865476f));
    sh[t] = g * w2[t];
    __syncthreads();
    for (int s = 128; s > 0; s >>= 1) {
        if (t < s) sh[t] += sh[t + s];
        __syncthreads();
    }
    if (t == 0) out[n] = sh[0] + b2[0];
}

// ---------------- launch --------------------------------------------------------
extern "C" void kernel_launch(void* const* d_in, const int* in_sizes, int n_in,
                              void* d_out, int out_size) {
    const int*   subj = (const int*)d_in[0];
    const int*   obj  = (const int*)d_in[1];
    const int*   rel  = (const int*)d_in[2];
    const float* time = (const float*)d_in[3];
    const float* ent  = (const float*)d_in[4];
    const float* relw = (const float*)d_in[5];
    const float* in_w = (const float*)d_in[6];
    const float* in_b = (const float*)d_in[7];
    const float* q_w  = (const float*)d_in[8];
    const float* q_b  = (const float*)d_in[9];
    const float* k_w  = (const float*)d_in[10];
    const float* k_b  = (const float*)d_in[11];
    const float* v_w  = (const float*)d_in[12];
    const float* v_b  = (const float*)d_in[13];
    const float* w1   = (const float*)d_in[14];
    const float* b1   = (const float*)d_in[15];
    const float* w2   = (const float*)d_in[16];
    const float* b2   = (const float*)d_in[17];
    float* out = (float*)d_out;

    cudaFuncSetAttribute(k_qkv_mma,    cudaFuncAttributeMaxDynamicSharedMemorySize, SMEM_MMA);
    cudaFuncSetAttribute(k_scores_mma, cudaFuncAttributeMaxDynamicSharedMemorySize, SMEM_MMA);
    cudaFuncSetAttribute(k_pv_mma,     cudaFuncAttributeMaxDynamicSharedMemorySize, SMEM_MMA);

    k_prep<<<(unsigned)((PR3 + 255) / 256), 256>>>(subj, obj, rel, ent, relw, time, q_w, k_w, v_w);
    k_gemm_x<<<dim3(DM / 128, ROWS / 128), 256>>>(in_w, in_b);

    for (int h = 0; h < 2; h++) {
        for (int l = 0; l < 2; l++) {
            int hl = h * 2 + l;
            k_build_ci<<<(int)(((size_t)ROWS2 * KP + 255) / 256), 256>>>(h);
            k_qkv_mma<<<dim3(6, ROWS2 / 128), 256, SMEM_MMA>>>(q_b, k_b, v_b, hl);
            k_vt<<<dim3(8, N_SEQ), 256>>>();
            k_sv<<<N_SEQ, 256>>>();
            k_scores_mma<<<dim3(2, N_SEQ), 256, SMEM_MMA>>>();
            k_softmax<<<(N_SEQ * LL2) / 8, 256>>>(time);
            k_pv_mma<<<dim3(2, 2, N_SEQ), 256, SMEM_MMA>>>();
            k_update<<<(ROWS * DM + 255) / 256, 256>>>(time, h);
        }
    }
    k_head<<<N_SEQ, 256>>>(w1, b1, w2, b2, out);
}

// round 9
// speedup vs baseline: 1.4807x; 1.1668x over previous
#include <cuda_runtime.h>
#include <cuda_bf16.h>
#include <math.h>
#include <stdint.h>

#define N_SEQ 512
#define LEN   128
#define LL2   256
#define DM    256
#define DT    32
#define DIN   288
#define KP    288
#define KE    384
#define ROWS  (N_SEQ*LEN)   // 65536
#define ROWS2 (N_SEQ*LL2)   // 131072

#define TILE_B   10240               // 128 rows * 80 bytes
#define SMEM_MMA (8 * TILE_B)        // 81920

// ---------------- scratch ----------------------------------------------------
__device__ float g_emb[ROWS*KE];
__device__ float g_cur[2][ROWS*DM];
__device__ __nv_bfloat16 g_cih[(size_t)ROWS2*KP];
__device__ __nv_bfloat16 g_cil[(size_t)ROWS2*KP];
__device__ __nv_bfloat16 g_temh[ROWS*DT];          // tem split-hi [row][32]
__device__ __nv_bfloat16 g_teml[ROWS*DT];
__device__ __nv_bfloat16 g_wTh[3*4*256*KP];
__device__ __nv_bfloat16 g_wTl[3*4*256*KP];
__device__ __nv_bfloat16 g_qh[(size_t)ROWS2*DM];
__device__ __nv_bfloat16 g_ql[(size_t)ROWS2*DM];
__device__ __nv_bfloat16 g_kh[(size_t)ROWS2*DM];
__device__ __nv_bfloat16 g_kl[(size_t)ROWS2*DM];
__device__ float g_v[ROWS2*DM];
__device__ __nv_bfloat16 g_vTh[(size_t)N_SEQ*DM*LEN];
__device__ __nv_bfloat16 g_vTl[(size_t)N_SEQ*DM*LEN];
__device__ float g_p[N_SEQ*LL2*LEN];
__device__ __nv_bfloat16 g_ph[(size_t)N_SEQ*LL2*LEN];
__device__ __nv_bfloat16 g_pl[(size_t)N_SEQ*LL2*LEN];
__device__ float g_pd[N_SEQ*LL2];
__device__ float g_sv[N_SEQ*DM];
__device__ float g_o[ROWS2*DM];

// ---------------- helpers -----------------------------------------------------
__device__ __forceinline__ uint32_t smem_u32(const void* p) {
    uint32_t a;
    asm("{ .reg .u64 t; cvta.to.shared.u64 t, %1; cvt.u32.u64 %0, t; }" : "=r"(a) : "l"(p));
    return a;
}
#define LDSM4(r0, r1, r2, r3, addr) \
    asm volatile("ldmatrix.sync.aligned.m8n8.x4.shared.b16 {%0,%1,%2,%3}, [%4];" \
        : "=r"(r0), "=r"(r1), "=r"(r2), "=r"(r3) : "r"(addr))
#define MMA16816(c, a, b0, b1) \
    asm volatile("mma.sync.aligned.m16n8k16.row.col.f32.bf16.bf16.f32 " \
        "{%0,%1,%2,%3},{%4,%5,%6,%7},{%8,%9},{%0,%1,%2,%3};" \
        : "+f"((c)[0]), "+f"((c)[1]), "+f"((c)[2]), "+f"((c)[3]) \
        : "r"((a)[0]), "r"((a)[1]), "r"((a)[2]), "r"((a)[3]), "r"(b0), "r"(b1))
#define CPASYNC16(dst, src) \
    asm volatile("cp.async.ca.shared.global [%0], [%1], 16;" :: "r"(dst), "l"(src))
#define CPCOMMIT() asm volatile("cp.async.commit_group;" ::: "memory")
#define CPWAIT0()  asm volatile("cp.async.wait_group 0;" ::: "memory")
#define CPWAIT1()  asm volatile("cp.async.wait_group 1;" ::: "memory")

__device__ __forceinline__ void split_store(__nv_bfloat16* ph, __nv_bfloat16* pl,
                                            size_t idx, float v) {
    __nv_bfloat16 hi = __float2bfloat16(v);
    ph[idx] = hi;
    pl[idx] = __float2bfloat16(v - __bfloat162float(hi));
}

// ---------------- fused 3-term mma core ---------------------------------------
__device__ __forceinline__ void mma_core3(
    const __nv_bfloat16* Ah, const __nv_bfloat16* Al,
    const __nv_bfloat16* Bh, const __nv_bfloat16* Bl,
    int lda, int ldb, int nkt, uint32_t sbase, float acc[4][4][4])
{
    int tid = threadIdx.x;
    int w = tid >> 5, lane = tid & 31;
    int wm = (w & 1) << 6;
    int wn = (w >> 1) << 5;
    int lr = tid >> 1;
    int c2 = (tid & 1) << 1;

    const char* pAh = (const char*)(Ah + (size_t)lr * lda) + c2 * 16;
    const char* pAl = (const char*)(Al + (size_t)lr * lda) + c2 * 16;
    const char* pBh = (const char*)(Bh + (size_t)lr * ldb) + c2 * 16;
    const char* pBl = (const char*)(Bl + (size_t)lr * ldb) + c2 * 16;
    uint32_t sdst = sbase + lr * 80 + c2 * 16;

    {
        CPASYNC16(sdst,              pAh);       CPASYNC16(sdst + 16,              pAh + 16);
        CPASYNC16(sdst + TILE_B,     pAl);       CPASYNC16(sdst + TILE_B + 16,     pAl + 16);
        CPASYNC16(sdst + 2*TILE_B,   pBh);       CPASYNC16(sdst + 2*TILE_B + 16,   pBh + 16);
        CPASYNC16(sdst + 3*TILE_B,   pBl);       CPASYNC16(sdst + 3*TILE_B + 16,   pBl + 16);
        CPCOMMIT();
    }

    int buf = 0;
    for (int kt = 0; kt < nkt; kt++) {
        bool more = (kt + 1 < nkt);
        if (more) {
            int off = (kt + 1) * 64;
            uint32_t d = sdst + (buf ^ 1) * (4 * TILE_B);
            CPASYNC16(d,              pAh + off);       CPASYNC16(d + 16,              pAh + off + 16);
            CPASYNC16(d + TILE_B,     pAl + off);       CPASYNC16(d + TILE_B + 16,     pAl + off + 16);
            CPASYNC16(d + 2*TILE_B,   pBh + off);       CPASYNC16(d + 2*TILE_B + 16,   pBh + off + 16);
            CPASYNC16(d + 3*TILE_B,   pBl + off);       CPASYNC16(d + 3*TILE_B + 16,   pBl + off + 16);
            CPCOMMIT();
            CPWAIT1();
        } else {
            CPWAIT0();
        }
        __syncthreads();

        uint32_t bAh = sbase + buf * (4 * TILE_B);
        uint32_t bAl = bAh + TILE_B;
        uint32_t bBh = bAh + 2 * TILE_B;
        uint32_t bBl = bAh + 3 * TILE_B;
#pragma unroll
        for (int ks = 0; ks < 2; ks++) {
            uint32_t arow = (uint32_t)((lane & 15)) * 80 + (uint32_t)(ks * 2 + ((lane >> 4) & 1)) * 16;
            uint32_t brow = (uint32_t)((lane & 7) + ((lane >> 4) & 1) * 8) * 80
                          + (uint32_t)(ks * 2 + ((lane >> 3) & 1)) * 16;
            uint32_t bh[2][4], bl[2][4];
#pragma unroll
            for (int p = 0; p < 2; p++) {
                uint32_t ad = (uint32_t)(wn + p * 16) * 80 + brow;
                LDSM4(bh[p][0], bh[p][1], bh[p][2], bh[p][3], bBh + ad);
                LDSM4(bl[p][0], bl[p][1], bl[p][2], bl[p][3], bBl + ad);
            }
            uint32_t a[4][4];
#pragma unroll
            for (int mf = 0; mf < 4; mf++) {
                uint32_t ad = (uint32_t)(wm + mf * 16) * 80 + arow;
                LDSM4(a[mf][0], a[mf][1], a[mf][2], a[mf][3], bAh + ad);
            }
#pragma unroll
            for (int mf = 0; mf < 4; mf++)
#pragma unroll
                for (int nf = 0; nf < 4; nf++) {
                    MMA16816(acc[mf][nf], a[mf], bh[nf >> 1][(nf & 1) * 2], bh[nf >> 1][(nf & 1) * 2 + 1]);
                    MMA16816(acc[mf][nf], a[mf], bl[nf >> 1][(nf & 1) * 2], bl[nf >> 1][(nf & 1) * 2 + 1]);
                }
#pragma unroll
            for (int mf = 0; mf < 4; mf++) {
                uint32_t ad = (uint32_t)(wm + mf * 16) * 80 + arow;
                LDSM4(a[mf][0], a[mf][1], a[mf][2], a[mf][3], bAl + ad);
            }
#pragma unroll
            for (int mf = 0; mf < 4; mf++)
#pragma unroll
                for (int nf = 0; nf < 4; nf++)
                    MMA16816(acc[mf][nf], a[mf], bh[nf >> 1][(nf & 1) * 2], bh[nf >> 1][(nf & 1) * 2 + 1]);
        }
        __syncthreads();
        buf ^= 1;
    }
}

// ---------------- QKV epilogue -------------------------------------------------
__device__ __forceinline__ void qkv_epilogue(float acc[4][4][4], int z, int baseRow,
                                             int n0, const float* bias) {
    int w = threadIdx.x >> 5, lane = threadIdx.x & 31;
    int wm = (w & 1) << 6, wn = (w >> 1) << 5;
    int r0 = lane >> 2, c0 = (lane & 3) << 1;
#pragma unroll
    for (int mf = 0; mf < 4; mf++)
#pragma unroll
        for (int nf = 0; nf < 4; nf++) {
            int row = baseRow + wm + mf * 16 + r0;
            int col = n0 + wn + nf * 8 + c0;
#pragma unroll
            for (int q = 0; q < 4; q++) {
                size_t idx = (size_t)(row + (q >> 1) * 8) * DM + col + (q & 1);
                float val = acc[mf][nf][q] + bias[col + (q & 1)];
                if (z == 2) g_v[idx] = val;
                else if (z == 0) split_store(g_qh, g_ql, idx, val);
                else             split_store(g_kh, g_kl, idx, val);
            }
        }
}

// ---------------- fused prep ---------------------------------------------------
#define PR0 ((size_t)ROWS*KE)
#define PR1 (PR0 + (size_t)ROWS*16)
#define PR2 (PR1 + (size_t)2*ROWS*DM)
#define PR3 (PR2 + (size_t)3*4*256*KP)
__global__ void k_prep(const int* __restrict__ subj, const int* __restrict__ obj,
                       const int* __restrict__ rel, const float* __restrict__ ent,
                       const float* __restrict__ relw, const float* __restrict__ time,
                       const float* __restrict__ qw, const float* __restrict__ kw,
                       const float* __restrict__ vw) {
    size_t i = (size_t)blockIdx.x * 256 + threadIdx.x;
    if (i < PR0) {
        int row = (int)(i / KE);
        int c   = (int)(i - (size_t)row * KE);
        float v;
        if (c < 128)      v = ent[subj[row] * 128 + c];
        else if (c < 256) v = ent[obj[row] * 128 + (c - 128)];
        else              v = relw[rel[row] * 128 + (c - 256)];
        g_emb[i] = v;
    } else if (i < PR1) {
        size_t j = i - PR0;
        int row = (int)(j >> 4);             // n*LEN + l
        int f   = (int)(j & 15);
        float t = time[row];
        float div = expf((float)(2 * f) * -0.28782313662425576f);
        float arg = t * div;
        float np  = (t > 0.f) ? 1.f : 0.f;
        float s = sinf(arg) * np;
        float c = cosf(arg) * np;
        int n = row >> 7, l = row & 127;
        size_t rT = ((size_t)n * LL2 + l) * KP + 256 + 2 * f;
        size_t rB = rT + (size_t)128 * KP;
        split_store(g_cih, g_cil, rT, s);
        split_store(g_cih, g_cil, rT + 1, c);
        split_store(g_cih, g_cil, rB, s);
        split_store(g_cih, g_cil, rB + 1, c);
        split_store(g_temh, g_teml, (size_t)row * DT + 2 * f, s);
        split_store(g_temh, g_teml, (size_t)row * DT + 2 * f + 1, c);
    } else if (i < PR2) {
        ((float*)g_cur)[i - PR1] = 0.f;
    } else if (i < PR3) {
        size_t j = i - PR2;
        int k  = (int)(j % KP);
        int n  = (int)((j / KP) & 255);
        int hl = (int)((j / (KP * 256)) & 3);
        int z  = (int)(j / ((size_t)KP * 256 * 4));
        const float* W = (z == 0) ? qw : (z == 1) ? kw : vw;
        float v = W[(hl * DIN + k) * 256 + n];
        split_store(g_wTh, g_wTl, j, v);
    }
}

// ---------------- QKV mma (full / top-only) ------------------------------------
__global__ __launch_bounds__(256, 2) void k_qkv_mma(const float* __restrict__ qb,
                                                    const float* __restrict__ kb,
                                                    const float* __restrict__ vb,
                                                    int hl, int topOnly) {
    extern __shared__ __nv_bfloat16 smem_dyn[];
    uint32_t sbase = smem_u32(smem_dyn);
    int z  = blockIdx.x >> 1;
    int n0 = (blockIdx.x & 1) << 7;
    int m0 = topOnly ? (blockIdx.y << 8) : (blockIdx.y << 7);

    float acc[4][4][4] = {};
    mma_core3(g_cih + (size_t)m0 * KP, g_cil + (size_t)m0 * KP,
              g_wTh + ((size_t)(z * 4 + hl) * 256 + n0) * KP,
              g_wTl + ((size_t)(z * 4 + hl) * 256 + n0) * KP,
              KP, KP, 9, sbase, acc);
    qkv_epilogue(acc, z, m0, n0, ((z == 0) ? qb : (z == 1) ? kb : vb) + hl * 256);
}

// ---------------- QKV bottom fast path at l=0: K=32 (tem only) -----------------
__global__ __launch_bounds__(256, 2) void k_qkv_bot(const float* __restrict__ qb,
                                                    const float* __restrict__ kb,
                                                    const float* __restrict__ vb, int hl) {
    extern __shared__ __nv_bfloat16 smem_dyn[];
    uint32_t sbase = smem_u32(smem_dyn);
    int z  = blockIdx.x >> 1;
    int n0 = (blockIdx.x & 1) << 7;
    int n  = blockIdx.y;

    float acc[4][4][4] = {};
    mma_core3(g_temh + (size_t)n * 128 * DT, g_teml + (size_t)n * 128 * DT,
              g_wTh + ((size_t)(z * 4 + hl) * 256 + n0) * KP + 256,
              g_wTl + ((size_t)(z * 4 + hl) * 256 + n0) * KP + 256,
              DT, KP, 1, sbase, acc);
    qkv_epilogue(acc, z, n * LL2 + 128, n0, ((z == 0) ? qb : (z == 1) ? kb : vb) + hl * 256);
}

// ---------------- V transpose + sv ---------------------------------------------
__global__ __launch_bounds__(256) void k_vt() {
    __shared__ float tile[128][33];
    int n = blockIdx.y, d0 = blockIdx.x << 5;
    for (int el = threadIdx.x; el < 4096; el += 256) {
        int key = el >> 5, d = el & 31;
        tile[key][d] = g_v[((size_t)n * LL2 + key) * DM + d0 + d];
    }
    __syncthreads();
    for (int el = threadIdx.x; el < 4096; el += 256) {
        int d = el >> 7, key = el & 127;
        size_t o = (size_t)n * DM * LEN + (size_t)(d0 + d) * LEN + key;
        split_store(g_vTh, g_vTl, o, tile[key][d]);
    }
}

__global__ void k_sv() {
    int n = blockIdx.x;
    int d = threadIdx.x;
    const float* vp = g_v + (n * LL2 + LEN) * DM + d;
    float s = 0.f;
#pragma unroll 8
    for (int j = 0; j < LEN; j++) s += vp[j * DM];
    g_sv[n * DM + d] = s;
}

// ---------------- scores mma ---------------------------------------------------
__global__ __launch_bounds__(256, 2) void k_scores_mma() {
    extern __shared__ __nv_bfloat16 smem_dyn[];
    uint32_t sbase = smem_u32(smem_dyn);
    int n = blockIdx.y;
    int m0 = blockIdx.x << 7;

    float acc[4][4][4] = {};
    mma_core3(g_qh + ((size_t)n * LL2 + m0) * DM, g_ql + ((size_t)n * LL2 + m0) * DM,
              g_kh + (size_t)n * LL2 * DM, g_kl + (size_t)n * LL2 * DM,
              DM, DM, 8, sbase, acc);

    int w = threadIdx.x >> 5, lane = threadIdx.x & 31;
    int wm = (w & 1) << 6, wn = (w >> 1) << 5;
    int r0 = lane >> 2, c0 = (lane & 3) << 1;
    float* P = g_p + ((size_t)n * LL2 + m0) * LEN;
#pragma unroll
    for (int mf = 0; mf < 4; mf++)
#pragma unroll
        for (int nf = 0; nf < 4; nf++) {
            int row = wm + mf * 16 + r0;
            int col = wn + nf * 8 + c0;
            P[(size_t)row * LEN + col]           = acc[mf][nf][0] * 0.0625f;
            P[(size_t)row * LEN + col + 1]       = acc[mf][nf][1] * 0.0625f;
            P[(size_t)(row + 8) * LEN + col]     = acc[mf][nf][2] * 0.0625f;
            P[(size_t)(row + 8) * LEN + col + 1] = acc[mf][nf][3] * 0.0625f;
        }
}

// ---------------- masked softmax -> bf16 hi/lo ---------------------------------
__global__ __launch_bounds__(256) void k_softmax(const float* __restrict__ time) {
    int warp = threadIdx.x >> 5, lane = threadIdx.x & 31;
    int rowId = blockIdx.x * 8 + warp;
    int n = rowId >> 8;
    int i = rowId & 255;
    const float* row = g_p + (size_t)rowId * LEN;
    __nv_bfloat16* oh = g_ph + (size_t)rowId * LEN;
    __nv_bfloat16* ol = g_pl + (size_t)rowId * LEN;
    const float* tt = time + n * LEN;
    bool bottom = (i >= LEN);
    int iq = bottom ? i - LEN : i;

    float vals[4];
    float mx = -1e30f;
#pragma unroll
    for (int c = 0; c < 4; c++) {
        int j = lane + c * 32;
        float s = row[j];
        bool masked = (j >= iq) || (tt[j] == 0.f);
        s = masked ? -1e9f : s;
        vals[c] = s;
        mx = fmaxf(mx, s);
    }
    float d = 0.f;
    if (bottom) {
        size_t base = (size_t)(n * LL2 + i) * DM / 2;
        const __nv_bfloat162* qh2 = (const __nv_bfloat162*)g_qh + base;
        const __nv_bfloat162* ql2 = (const __nv_bfloat162*)g_ql + base;
        const __nv_bfloat162* kh2 = (const __nv_bfloat162*)g_kh + base;
        const __nv_bfloat162* kl2 = (const __nv_bfloat162*)g_kl + base;
#pragma unroll
        for (int c = 0; c < 4; c++) {
            int idx = lane * 4 + c;
            __nv_bfloat162 a = qh2[idx], b = ql2[idx], e = kh2[idx], f = kl2[idx];
            float qx = __bfloat162float(a.x) + __bfloat162float(b.x);
            float qy = __bfloat162float(a.y) + __bfloat162float(b.y);
            float kx = __bfloat162float(e.x) + __bfloat162float(f.x);
            float ky = __bfloat162float(e.y) + __bfloat162float(f.y);
            d += qx * kx + qy * ky;
        }
#pragma unroll
        for (int off = 16; off; off >>= 1) d += __shfl_xor_sync(0xffffffffu, d, off);
        d *= 0.0625f;
    }
#pragma unroll
    for (int off = 16; off; off >>= 1) mx = fmaxf(mx, __shfl_xor_sync(0xffffffffu, mx, off));

    if (!bottom && mx < -5e8f) {
        __nv_bfloat16 u = __float2bfloat16(1.0f / 256.0f);
#pragma unroll
        for (int c = 0; c < 4; c++) { oh[lane + c * 32] = u; ol[lane + c * 32] = __float2bfloat16(0.f); }
        if (lane == 0) g_pd[rowId] = 1.0f / 256.0f;
        return;
    }
    if (bottom) mx = fmaxf(mx, d);
    float sum = 0.f;
#pragma unroll
    for (int c = 0; c < 4; c++) { vals[c] = expf(vals[c] - mx); sum += vals[c]; }
#pragma unroll
    for (int off = 16; off; off >>= 1) sum += __shfl_xor_sync(0xffffffffu, sum, off);
    float ed = bottom ? expf(d - mx) : 0.f;
    float inv = 1.f / (sum + ed);
#pragma unroll
    for (int c = 0; c < 4; c++) {
        float p = vals[c] * inv;
        __nv_bfloat16 hi = __float2bfloat16(p);
        oh[lane + c * 32] = hi;
        ol[lane + c * 32] = __float2bfloat16(p - __bfloat162float(hi));
    }
    if (lane == 0) g_pd[rowId] = ed * inv;
}

// ---------------- PV mma -------------------------------------------------------
__global__ __launch_bounds__(256, 2) void k_pv_mma() {
    extern __shared__ __nv_bfloat16 smem_dyn[];
    uint32_t sbase = smem_u32(smem_dyn);
    int n  = blockIdx.z;
    int m0 = blockIdx.y << 7;
    int n0 = blockIdx.x << 7;

    float acc[4][4][4] = {};
    mma_core3(g_ph + ((size_t)n * LL2 + m0) * LEN, g_pl + ((size_t)n * LL2 + m0) * LEN,
              g_vTh + ((size_t)n * DM + n0) * LEN, g_vTl + ((size_t)n * DM + n0) * LEN,
              LEN, LEN, 4, sbase, acc);

    int w = threadIdx.x >> 5, lane = threadIdx.x & 31;
    int wm = (w & 1) << 6, wn = (w >> 1) << 5;
    int r0 = lane >> 2, c0 = (lane & 3) << 1;
    const float* V = g_v + (size_t)n * LL2 * DM;
    float* O = g_o + (size_t)n * LL2 * DM;
#pragma unroll
    for (int mf = 0; mf < 4; mf++)
#pragma unroll
        for (int nf = 0; nf < 4; nf++) {
            int row = m0 + wm + mf * 16 + r0;
            int col = n0 + wn + nf * 8 + c0;
#pragma unroll
            for (int q = 0; q < 4; q++) {
                int r = row + (q >> 1) * 8;
                int c = col + (q & 1);
                float pd = g_pd[n * LL2 + r];
                float extra = (r < LEN) ? g_sv[n * DM + c] : V[(size_t)r * DM + c];
                O[(size_t)r * DM + c] = acc[mf][nf][q] + pd * extra;
            }
        }
}

// ---------------- fused residual update + next-iteration ci --------------------
__global__ void k_update_ci(const float* __restrict__ time, int h,
                            int writeTop, int writeBottom) {
    int i = blockIdx.x * 256 + threadIdx.x;
    if (i >= ROWS * DM) return;
    int row = i >> 8;                 // n*LEN + l
    int d   = i & 255;
    int n   = row >> 7;
    int l   = row & 127;
    float top = g_o[(n * LL2 + l) * DM + d];
    float bot = g_o[(n * LL2 + LEN + l) * DM + d];
    float np  = (time[row] > 0.f) ? 1.f : 0.f;
    float nc  = g_cur[h][i] + tanhf(bot * np);
    g_cur[h][i] = nc;
    if (writeTop)
        split_store(g_cih, g_cil, ((size_t)n * LL2 + l) * KP + d, top);
    if (writeBottom)
        split_store(g_cih, g_cil, ((size_t)n * LL2 + LEN + l) * KP + d, nc);
}

// ---------------- FFMA GEMM for input projection (writes ci) -------------------
__device__ __forceinline__ void gemm_compute(const float (*As)[140], const float (*Bs)[128],
                                             float acc[8][8], int tx, int ty) {
#pragma unroll
    for (int k = 0; k < 8; k++) {
        float a[8], b[8];
        *(float4*)(a)     = *(const float4*)&As[k][ty * 4];
        *(float4*)(a + 4) = *(const float4*)&As[k][64 + ty * 4];
        *(float4*)(b)     = *(const float4*)&Bs[k][tx * 4];
        *(float4*)(b + 4) = *(const float4*)&Bs[k][64 + tx * 4];
#pragma unroll
        for (int i = 0; i < 8; i++)
#pragma unroll
            for (int j = 0; j < 8; j++)
                acc[i][j] += a[i] * b[j];
    }
}

__global__ __launch_bounds__(256) void k_gemm_x(const float* __restrict__ W,
                                                const float* __restrict__ bias) {
    __shared__ float As[2][8][140];
    __shared__ float Bs[2][8][128];
    float acc[8][8] = {};
    int m0 = blockIdx.y << 7, n0 = blockIdx.x << 7;
    int tid = threadIdx.x;
    int tx = tid & 15, ty = tid >> 4;
    int ar = tid >> 1, kg = (tid & 1) << 2;
    int br = tid >> 5, bc = (tid & 31) << 2;

    float4 a = *(const float4*)(g_emb + (m0 + ar) * KE + kg);
    float4 b = *(const float4*)(W + br * DM + n0 + bc);
    As[0][kg][ar] = a.x; As[0][kg + 1][ar] = a.y; As[0][kg + 2][ar] = a.z; As[0][kg + 3][ar] = a.w;
    *(float4*)&Bs[0][br][bc] = b;
    __syncthreads();

    int buf = 0;
    for (int k0 = 8; k0 < KE; k0 += 8) {
        float4 an = *(const float4*)(g_emb + (m0 + ar) * KE + k0 + kg);
        float4 bn = *(const float4*)(W + (k0 + br) * DM + n0 + bc);
        gemm_compute(As[buf], Bs[buf], acc, tx, ty);
        int nb = buf ^ 1;
        As[nb][kg][ar] = an.x; As[nb][kg + 1][ar] = an.y; As[nb][kg + 2][ar] = an.z; As[nb][kg + 3][ar] = an.w;
        *(float4*)&Bs[nb][br][bc] = bn;
        __syncthreads();
        buf = nb;
    }
    gemm_compute(As[buf], Bs[buf], acc, tx, ty);

#pragma unroll
    for (int i = 0; i < 8; i++) {
        int r = m0 + ((i < 4) ? (ty << 2) + i : 64 + (ty << 2) + i - 4);
        int n = r >> 7, l = r & 127;
#pragma unroll
        for (int j = 0; j < 8; j++) {
            int c = n0 + ((j < 4) ? (tx << 2) + j : 64 + (tx << 2) + j - 4);
            split_store(g_cih, g_cil, ((size_t)n * LL2 + l) * KP + c, acc[i][j] + bias[c]);
        }
    }
}

// ---------------- final MLP head -----------------------------------------------
__global__ __launch_bounds__(256) void k_head(const float* __restrict__ w1,
                                              const float* __restrict__ b1,
                                              const float* __restrict__ w2,
                                              const float* __restrict__ b2,
                                              float* __restrict__ out) {
    int n = blockIdx.x;
    int t = threadIdx.x;
    __shared__ float sl[512];
    __shared__ float sh[256];
    sl[t]       = g_cur[0][(n * LEN + LEN - 1) * DM + t];
    sl[256 + t] = g_cur[1][(n * LEN + LEN - 1) * DM + t];
    __syncthreads();
    float acc = b1[t];
    for (int k = 0; k < 512; k++) acc += sl[k] * w1[k * DM + t];
    float x = acc;
    float g = 0.5f * x * (1.f + erff(x * 0.7071067811865476f));
    sh[t] = g * w2[t];
    __syncthreads();
    for (int s = 128; s > 0; s >>= 1) {
        if (t < s) sh[t] += sh[t + s];
        __syncthreads();
    }
    if (t == 0) out[n] = sh[0] + b2[0];
}

// ---------------- launch --------------------------------------------------------
extern "C" void kernel_launch(void* const* d_in, const int* in_sizes, int n_in,
                              void* d_out, int out_size) {
    const int*   subj = (const int*)d_in[0];
    const int*   obj  = (const int*)d_in[1];
    const int*   rel  = (const int*)d_in[2];
    const float* time = (const float*)d_in[3];
    const float* ent  = (const float*)d_in[4];
    const float* relw = (const float*)d_in[5];
    const float* in_w = (const float*)d_in[6];
    const float* in_b = (const float*)d_in[7];
    const float* q_w  = (const float*)d_in[8];
    const float* q_b  = (const float*)d_in[9];
    const float* k_w  = (const float*)d_in[10];
    const float* k_b  = (const float*)d_in[11];
    const float* v_w  = (const float*)d_in[12];
    const float* v_b  = (const float*)d_in[13];
    const float* w1   = (const float*)d_in[14];
    const float* b1   = (const float*)d_in[15];
    const float* w2   = (const float*)d_in[16];
    const float* b2   = (const float*)d_in[17];
    float* out = (float*)d_out;

    cudaFuncSetAttribute(k_qkv_mma,    cudaFuncAttributeMaxDynamicSharedMemorySize, SMEM_MMA);
    cudaFuncSetAttribute(k_qkv_bot,    cudaFuncAttributeMaxDynamicSharedMemorySize, SMEM_MMA);
    cudaFuncSetAttribute(k_scores_mma, cudaFuncAttributeMaxDynamicSharedMemorySize, SMEM_MMA);
    cudaFuncSetAttribute(k_pv_mma,     cudaFuncAttributeMaxDynamicSharedMemorySize, SMEM_MMA);

    k_prep<<<(unsigned)((PR3 + 255) / 256), 256>>>(subj, obj, rel, ent, relw, time, q_w, k_w, v_w);
    k_gemm_x<<<dim3(DM / 128, ROWS / 128), 256>>>(in_w, in_b);

    for (int h = 0; h < 2; h++) {
        for (int l = 0; l < 2; l++) {
            int hl = h * 2 + l;
            if (l == 0) {
                k_qkv_mma<<<dim3(6, N_SEQ), 256, SMEM_MMA>>>(q_b, k_b, v_b, hl, 1);
                k_qkv_bot<<<dim3(6, N_SEQ), 256, SMEM_MMA>>>(q_b, k_b, v_b, hl);
            } else {
                k_qkv_mma<<<dim3(6, ROWS2 / 128), 256, SMEM_MMA>>>(q_b, k_b, v_b, hl, 0);
            }
            k_vt<<<dim3(8, N_SEQ), 256>>>();
            k_sv<<<N_SEQ, 256>>>();
            k_scores_mma<<<dim3(2, N_SEQ), 256, SMEM_MMA>>>();
            k_softmax<<<(N_SEQ * LL2) / 8, 256>>>(time);
            k_pv_mma<<<dim3(2, 2, N_SEQ), 256, SMEM_MMA>>>();
            int it = h * 2 + l;
            k_update_ci<<<(ROWS * DM + 255) / 256, 256>>>(time, h, it < 3 ? 1 : 0, l == 0 ? 1 : 0);
        }
    }
    k_head<<<N_SEQ, 256>>>(w1, b1, w2, b2, out);
}